// round 5
// baseline (speedup 1.0000x reference)
#include <cuda_runtime.h>
#include <cuda_bf16.h>
#include <cstdint>

// ============================================================================
// SSIM loss, separable Gaussian, 4-signal (u=x+y, v=x-y), bf16-staged smem,
// scalar FFMA with immediate weights, f32 accumulation.
// ============================================================================

static constexpr int THREADS = 384;
static constexpr int NBLK    = 2048;
static constexpr float C1 = 1.0e-4f;
static constexpr float C2 = 9.0e-4f;

__device__ constexpr float G[11] = {
    0.00102840f, 0.00759878f, 0.03600077f, 0.10936042f, 0.21300560f,
    0.26601170f,
    0.21300560f, 0.10936042f, 0.03600077f, 0.00759878f, 0.00102840f
};

struct SmemLayout {
    uint32_t plane[64][67];     // bf16x2 (hi=v, lo=u)            17,152 B
    uint32_t hpq[64][55];       // bf16x2 (hi=q,  lo=p)           14,080 B
    uint32_t hs [64][55];       // bf16x2 (hi=sv, lo=su)          14,080 B
    float red[THREADS / 32];
    unsigned int ticket;
};
static constexpr int SMEM_BYTES = (int)sizeof(SmemLayout);   // ~45.4 KB

__device__ float        g_part[NBLK];
__device__ unsigned int g_count = 0;

// pack two f32 -> bf16x2 word (hi, lo)
__device__ __forceinline__ uint32_t pk(float hi, float lo) {
    uint32_t r;
    asm("cvt.rn.bf16x2.f32 %0, %1, %2;" : "=r"(r) : "f"(hi), "f"(lo));
    return r;
}
__device__ __forceinline__ float lo_f(uint32_t w) { return __uint_as_float(w << 16); }
__device__ __forceinline__ float hi_f(uint32_t w) { return __uint_as_float(w & 0xFFFF0000u); }

__global__ __launch_bounds__(THREADS, 3)
void ssim_main(const float* __restrict__ pred, const float* __restrict__ gt,
               float* __restrict__ out)
{
    extern __shared__ unsigned char smem_raw[];
    SmemLayout& s = *reinterpret_cast<SmemLayout*>(smem_raw);

    const int b   = blockIdx.x;
    const int tid = threadIdx.x;
    const float* pb = pred + (size_t)b * 12288;
    const float* gb = gt   + (size_t)b * 12288;

    float local = 0.0f;

    for (int ch = 0; ch < 3; ++ch) {
        __syncthreads();

        // ---- load channel plane, pack (u,v) = (x+y, x-y) as bf16x2
        for (int i = tid; i < 4096; i += THREADS) {
            const float x = pb[i * 3 + ch];
            const float y = gb[i * 3 + ch];
            s.plane[i >> 6][i & 63] = pk(x - y, x + y);   // hi=v, lo=u
        }
        __syncthreads();

        // ---- horizontal pass: seg=tid/64 (6 segs of 9 cols), r=tid%64.
        // Warp lanes span 32 consecutive rows, odd stride 67 -> conflict-free.
        {
            const int seg = tid / 64;
            const int r   = tid & 63;
            const int c0  = seg * 9;

            float a0[9], a1[9], a2[9], a3[9];
            #pragma unroll
            for (int o = 0; o < 9; ++o) { a0[o]=0.f; a1[o]=0.f; a2[o]=0.f; a3[o]=0.f; }

            #pragma unroll
            for (int j = 0; j < 19; ++j) {
                const uint32_t w = s.plane[r][c0 + j];
                const float u = lo_f(w), v = hi_f(w);
                const float uu = u * u, vv = v * v;
                #pragma unroll
                for (int k = 0; k < 11; ++k) {
                    const int o = j - k;                 // compile-time pruned
                    if (o >= 0 && o < 9) {
                        a0[o] = fmaf(u,  G[k], a0[o]);   // FFMA-imm
                        a1[o] = fmaf(v,  G[k], a1[o]);
                        a2[o] = fmaf(uu, G[k], a2[o]);
                        a3[o] = fmaf(vv, G[k], a3[o]);
                    }
                }
            }
            #pragma unroll
            for (int o = 0; o < 9; ++o) {
                s.hpq[r][c0 + o] = pk(a1[o], a0[o]);     // hi=q,  lo=p
                s.hs [r][c0 + o] = pk(a3[o], a2[o]);     // hi=sv, lo=su
            }
        }
        __syncthreads();

        // ---- vertical pass + ssim: 324 tasks = 6 row-segments x 54 cols
        if (tid < 324) {
            const int c  = tid % 54;
            const int r0 = (tid / 54) * 9;

            float a0[9], a1[9], a2[9], a3[9];
            #pragma unroll
            for (int o = 0; o < 9; ++o) { a0[o]=0.f; a1[o]=0.f; a2[o]=0.f; a3[o]=0.f; }

            #pragma unroll
            for (int j = 0; j < 19; ++j) {
                const uint32_t wpq = s.hpq[r0 + j][c];
                const uint32_t ws  = s.hs [r0 + j][c];
                const float p  = lo_f(wpq), q  = hi_f(wpq);
                const float su = lo_f(ws),  sv = hi_f(ws);
                #pragma unroll
                for (int k = 0; k < 11; ++k) {
                    const int o = j - k;
                    if (o >= 0 && o < 9) {
                        a0[o] = fmaf(p,  G[k], a0[o]);
                        a1[o] = fmaf(q,  G[k], a1[o]);
                        a2[o] = fmaf(su, G[k], a2[o]);
                        a3[o] = fmaf(sv, G[k], a3[o]);
                    }
                }
            }
            #pragma unroll
            for (int o = 0; o < 9; ++o) {
                const float p = a0[o], q = a1[o];
                const float P = p * p, Q = q * q;
                const float A = 0.5f * (P - Q);          // 2*mu1*mu2
                const float B = 0.5f * (P + Q);          // mu1^2 + mu2^2
                const float num = (A + C1) * (fmaf(0.5f, a2[o] - a3[o], C2) - A);
                const float den = (B + C1) * (fmaf(0.5f, a2[o] + a3[o], C2) - B);
                local += __fdividef(num, den);
            }
        }
    }

    // ---- fixed-order block reduction
    __syncthreads();
    #pragma unroll
    for (int off = 16; off > 0; off >>= 1)
        local += __shfl_down_sync(0xffffffffu, local, off);
    if ((tid & 31) == 0) s.red[tid >> 5] = local;
    __syncthreads();
    if (tid == 0) {
        float sum = 0.0f;
        #pragma unroll
        for (int w = 0; w < THREADS / 32; ++w) sum += s.red[w];
        g_part[b] = sum;
        __threadfence();
        s.ticket = atomicAdd(&g_count, 1u);
    }
    __syncthreads();

    // ---- last block: deterministic global reduction
    if (s.ticket == NBLK - 1) {
        float sum = 0.0f;
        for (int i = tid; i < NBLK; i += THREADS) sum += g_part[i];
        #pragma unroll
        for (int off = 16; off > 0; off >>= 1)
            sum += __shfl_down_sync(0xffffffffu, sum, off);
        if ((tid & 31) == 0) s.red[tid >> 5] = sum;
        __syncthreads();
        if (tid == 0) {
            float t = 0.0f;
            #pragma unroll
            for (int w = 0; w < THREADS / 32; ++w) t += s.red[w];
            out[0] = 1.0f - t * (1.0f / 17915904.0f);   // N = 2048*3*54*54
            g_count = 0;                                 // reset for replay
        }
    }
}

extern "C" void kernel_launch(void* const* d_in, const int* in_sizes, int n_in,
                              void* d_out, int out_size)
{
    const float* pred = (const float*)d_in[0];
    const float* gt   = (const float*)d_in[1];
    float* out        = (float*)d_out;

    cudaFuncSetAttribute(ssim_main, cudaFuncAttributeMaxDynamicSharedMemorySize,
                         SMEM_BYTES);
    ssim_main<<<NBLK, THREADS, SMEM_BYTES>>>(pred, gt, out);
}